// round 2
// baseline (speedup 1.0000x reference)
#include <cuda_runtime.h>

#define NLAYERS 32
#define NPAR (NLAYERS * 6 + 3)
#define TPB 256
#define V4_PER_THREAD 4   // 4 float4 = 8 rows per thread

// Folded parameters: per layer {a00, a01, c0, a10, a11, c1}; then {wo0, wo1, bo}
__device__ float g_fold[NPAR];

// Fold scale/shift of layer l into layer l+1's weights/bias (torch Linear: z_i = sum_j W[i][j] h_j + b_i).
// Layer 0 unclipped; layers 1..31 have W,b clipped to [-5,5].
__global__ void fold_kernel(const float* __restrict__ W, const float* __restrict__ b,
                            const float* __restrict__ scale, const float* __restrict__ shift,
                            const float* __restrict__ W_out, const float* __restrict__ b_out) {
    if (threadIdx.x == 0 && blockIdx.x == 0) {
        float sp0 = 1.0f, sp1 = 1.0f, shp0 = 0.0f, shp1 = 0.0f;
        for (int l = 0; l < NLAYERS; ++l) {
            float w00 = W[l * 4 + 0], w01 = W[l * 4 + 1];
            float w10 = W[l * 4 + 2], w11 = W[l * 4 + 3];
            float bb0 = b[l * 2 + 0], bb1 = b[l * 2 + 1];
            if (l > 0) {
                w00 = fminf(fmaxf(w00, -5.0f), 5.0f);
                w01 = fminf(fmaxf(w01, -5.0f), 5.0f);
                w10 = fminf(fmaxf(w10, -5.0f), 5.0f);
                w11 = fminf(fmaxf(w11, -5.0f), 5.0f);
                bb0 = fminf(fmaxf(bb0, -5.0f), 5.0f);
                bb1 = fminf(fmaxf(bb1, -5.0f), 5.0f);
            }
            g_fold[l * 6 + 0] = w00 * sp0;
            g_fold[l * 6 + 1] = w01 * sp1;
            g_fold[l * 6 + 2] = w00 * shp0 + w01 * shp1 + bb0;
            g_fold[l * 6 + 3] = w10 * sp0;
            g_fold[l * 6 + 4] = w11 * sp1;
            g_fold[l * 6 + 5] = w10 * shp0 + w11 * shp1 + bb1;
            sp0 = scale[l * 2 + 0]; sp1 = scale[l * 2 + 1];
            shp0 = shift[l * 2 + 0]; shp1 = shift[l * 2 + 1];
        }
        float wo0 = W_out[0], wo1 = W_out[1];
        g_fold[NLAYERS * 6 + 0] = wo0 * sp0;
        g_fold[NLAYERS * 6 + 1] = wo1 * sp1;
        g_fold[NLAYERS * 6 + 2] = wo0 * shp0 + wo1 * shp1 + b_out[0];
    }
}

// Accurate-enough fast tanh: 2 MUFU (EX2, RCP) + a few FMAs, ~1e-6 rel error.
__device__ __forceinline__ float fast_tanh(float x) {
    x = fminf(fmaxf(x, -10.0f), 10.0f);     // avoid inf in exp; tanh(10)==1.0f anyway
    float e = __expf(x + x);                // FMUL + MUFU.EX2
    return 1.0f - __fdividef(2.0f, e + 1.0f);  // MUFU.RCP + FMUL
}

__global__ void __launch_bounds__(TPB)
model_kernel(const float4* __restrict__ x4, float2* __restrict__ out2, int n4) {
    __shared__ float sp[NPAR];
    for (int i = threadIdx.x; i < NPAR; i += TPB) sp[i] = g_fold[i];
    __syncthreads();

    const int T = gridDim.x * TPB;
    const int tid = blockIdx.x * TPB + threadIdx.x;

    float h0[2 * V4_PER_THREAD], h1[2 * V4_PER_THREAD];
    int idx[V4_PER_THREAD];
    bool valid[V4_PER_THREAD];

#pragma unroll
    for (int k = 0; k < V4_PER_THREAD; ++k) {
        idx[k] = tid + k * T;                 // coalesced: consecutive threads -> consecutive float4s
        valid[k] = idx[k] < n4;
        float4 v = valid[k] ? x4[idx[k]] : make_float4(0.f, 0.f, 0.f, 0.f);
        h0[2 * k + 0] = v.x; h1[2 * k + 0] = v.y;   // row 2*idx
        h0[2 * k + 1] = v.z; h1[2 * k + 1] = v.w;   // row 2*idx+1
    }

#pragma unroll 1   // keep the layer loop rolled: small body stays resident in L0 I$
    for (int l = 0; l < NLAYERS; ++l) {
        const float a00 = sp[l * 6 + 0], a01 = sp[l * 6 + 1], c0 = sp[l * 6 + 2];
        const float a10 = sp[l * 6 + 3], a11 = sp[l * 6 + 4], c1 = sp[l * 6 + 5];
#pragma unroll
        for (int r = 0; r < 2 * V4_PER_THREAD; ++r) {
            float z0 = fmaf(a00, h0[r], fmaf(a01, h1[r], c0));
            float z1 = fmaf(a10, h0[r], fmaf(a11, h1[r], c1));
            h0[r] = fast_tanh(z0);
            h1[r] = fast_tanh(z1);
        }
    }

    const float wo0 = sp[NLAYERS * 6 + 0], wo1 = sp[NLAYERS * 6 + 1], bo = sp[NLAYERS * 6 + 2];
#pragma unroll
    for (int k = 0; k < V4_PER_THREAD; ++k) {
        if (valid[k]) {
            float2 o;
            o.x = fmaf(wo0, h0[2 * k + 0], fmaf(wo1, h1[2 * k + 0], bo));
            o.y = fmaf(wo0, h0[2 * k + 1], fmaf(wo1, h1[2 * k + 1], bo));
            out2[idx[k]] = o;
        }
    }
}

extern "C" void kernel_launch(void* const* d_in, const int* in_sizes, int n_in,
                              void* d_out, int out_size) {
    const float* x     = (const float*)d_in[0];
    const float* W     = (const float*)d_in[1];
    const float* b     = (const float*)d_in[2];
    const float* scale = (const float*)d_in[3];
    const float* shift = (const float*)d_in[4];
    const float* W_out = (const float*)d_in[5];
    const float* b_out = (const float*)d_in[6];

    fold_kernel<<<1, 32>>>(W, b, scale, shift, W_out, b_out);

    const int B  = in_sizes[0] / 2;   // rows
    const int n4 = B / 2;             // float4 count (2 rows per float4); B is even (2^24)
    const long long totalThreads = ((long long)n4 + V4_PER_THREAD - 1) / V4_PER_THREAD;
    const int blocks = (int)((totalThreads + TPB - 1) / TPB);

    model_kernel<<<blocks, TPB>>>((const float4*)x, (float2*)d_out, n4);
}

// round 3
// speedup vs baseline: 1.8597x; 1.8597x over previous
#include <cuda_runtime.h>

#define NLAYERS 32
#define NPAR (NLAYERS * 6 + 3)
#define TPB 256
#define V4_PER_THREAD 4   // 4 float4 = 8 rows per thread

// Folded parameters: per layer {a00, a01, c0, a10, a11, c1}; then {wo0, wo1, bo}
__device__ float g_fold[NPAR];

// Fold scale/shift of layer l into layer l+1's weights/bias (torch Linear: z_i = sum_j W[i][j] h_j + b_i).
// Layer 0 unclipped; layers 1..31 have W,b clipped to [-5,5].
__global__ void fold_kernel(const float* __restrict__ W, const float* __restrict__ b,
                            const float* __restrict__ scale, const float* __restrict__ shift,
                            const float* __restrict__ W_out, const float* __restrict__ b_out) {
    if (threadIdx.x == 0 && blockIdx.x == 0) {
        float sp0 = 1.0f, sp1 = 1.0f, shp0 = 0.0f, shp1 = 0.0f;
        for (int l = 0; l < NLAYERS; ++l) {
            float w00 = W[l * 4 + 0], w01 = W[l * 4 + 1];
            float w10 = W[l * 4 + 2], w11 = W[l * 4 + 3];
            float bb0 = b[l * 2 + 0], bb1 = b[l * 2 + 1];
            if (l > 0) {
                w00 = fminf(fmaxf(w00, -5.0f), 5.0f);
                w01 = fminf(fmaxf(w01, -5.0f), 5.0f);
                w10 = fminf(fmaxf(w10, -5.0f), 5.0f);
                w11 = fminf(fmaxf(w11, -5.0f), 5.0f);
                bb0 = fminf(fmaxf(bb0, -5.0f), 5.0f);
                bb1 = fminf(fmaxf(bb1, -5.0f), 5.0f);
            }
            g_fold[l * 6 + 0] = w00 * sp0;
            g_fold[l * 6 + 1] = w01 * sp1;
            g_fold[l * 6 + 2] = w00 * shp0 + w01 * shp1 + bb0;
            g_fold[l * 6 + 3] = w10 * sp0;
            g_fold[l * 6 + 4] = w11 * sp1;
            g_fold[l * 6 + 5] = w10 * shp0 + w11 * shp1 + bb1;
            sp0 = scale[l * 2 + 0]; sp1 = scale[l * 2 + 1];
            shp0 = shift[l * 2 + 0]; shp1 = shift[l * 2 + 1];
        }
        float wo0 = W_out[0], wo1 = W_out[1];
        g_fold[NLAYERS * 6 + 0] = wo0 * sp0;
        g_fold[NLAYERS * 6 + 1] = wo1 * sp1;
        g_fold[NLAYERS * 6 + 2] = wo0 * shp0 + wo1 * shp1 + b_out[0];
    }
}

// Hardware tanh: single MUFU.TANH op (sm_75+), ~6e-4 max abs error, full range.
__device__ __forceinline__ float htanh(float x) {
    float y;
    asm("tanh.approx.f32 %0, %1;" : "=f"(y) : "f"(x));
    return y;
}

__global__ void __launch_bounds__(TPB)
model_kernel(const float4* __restrict__ x4, float2* __restrict__ out2, int n4) {
    __shared__ float sp[NPAR];
    for (int i = threadIdx.x; i < NPAR; i += TPB) sp[i] = g_fold[i];
    __syncthreads();

    const int T = gridDim.x * TPB;
    const int tid = blockIdx.x * TPB + threadIdx.x;

    float h0[2 * V4_PER_THREAD], h1[2 * V4_PER_THREAD];
    int idx[V4_PER_THREAD];
    bool valid[V4_PER_THREAD];

#pragma unroll
    for (int k = 0; k < V4_PER_THREAD; ++k) {
        idx[k] = tid + k * T;                 // coalesced: consecutive threads -> consecutive float4s
        valid[k] = idx[k] < n4;
        float4 v = valid[k] ? x4[idx[k]] : make_float4(0.f, 0.f, 0.f, 0.f);
        h0[2 * k + 0] = v.x; h1[2 * k + 0] = v.y;   // row 2*idx
        h0[2 * k + 1] = v.z; h1[2 * k + 1] = v.w;   // row 2*idx+1
    }

#pragma unroll 1   // keep the layer loop rolled: small body stays resident in L0 I$
    for (int l = 0; l < NLAYERS; ++l) {
        const float a00 = sp[l * 6 + 0], a01 = sp[l * 6 + 1], c0 = sp[l * 6 + 2];
        const float a10 = sp[l * 6 + 3], a11 = sp[l * 6 + 4], c1 = sp[l * 6 + 5];
#pragma unroll
        for (int r = 0; r < 2 * V4_PER_THREAD; ++r) {
            float z0 = fmaf(a00, h0[r], fmaf(a01, h1[r], c0));
            float z1 = fmaf(a10, h0[r], fmaf(a11, h1[r], c1));
            h0[r] = htanh(z0);
            h1[r] = htanh(z1);
        }
    }

    const float wo0 = sp[NLAYERS * 6 + 0], wo1 = sp[NLAYERS * 6 + 1], bo = sp[NLAYERS * 6 + 2];
#pragma unroll
    for (int k = 0; k < V4_PER_THREAD; ++k) {
        if (valid[k]) {
            float2 o;
            o.x = fmaf(wo0, h0[2 * k + 0], fmaf(wo1, h1[2 * k + 0], bo));
            o.y = fmaf(wo0, h0[2 * k + 1], fmaf(wo1, h1[2 * k + 1], bo));
            out2[idx[k]] = o;
        }
    }
}

extern "C" void kernel_launch(void* const* d_in, const int* in_sizes, int n_in,
                              void* d_out, int out_size) {
    const float* x     = (const float*)d_in[0];
    const float* W     = (const float*)d_in[1];
    const float* b     = (const float*)d_in[2];
    const float* scale = (const float*)d_in[3];
    const float* shift = (const float*)d_in[4];
    const float* W_out = (const float*)d_in[5];
    const float* b_out = (const float*)d_in[6];

    fold_kernel<<<1, 32>>>(W, b, scale, shift, W_out, b_out);

    const int B  = in_sizes[0] / 2;   // rows
    const int n4 = B / 2;             // float4 count (2 rows per float4); B is even (2^24)
    const long long totalThreads = ((long long)n4 + V4_PER_THREAD - 1) / V4_PER_THREAD;
    const int blocks = (int)((totalThreads + TPB - 1) / TPB);

    model_kernel<<<blocks, TPB>>>((const float4*)x, (float2*)d_out, n4);
}

// round 5
// speedup vs baseline: 1.8782x; 1.0099x over previous
#include <cuda_runtime.h>
#include <cuda_fp16.h>
#include <stdint.h>

#define NLAYERS 32
#define FP16_FIRST 1      // layers [FP16_FIRST, FP16_LAST) run in packed fp16
#define FP16_LAST 30      // layers 30,31 stay fp32 (errors there hit output undamped)
#define NPAR (NLAYERS * 6 + 3)
#define NPARH (NLAYERS * 3)
#define TPB 256
#define V4_PER_THREAD 4   // 4 float4 = 8 rows per thread

// Folded fp32 parameters: per layer {a00, a01, c0, a10, a11, c1}; then {wo0, wo1, bo}
__device__ float g_fold[NPAR];
// Packed fp16 params per layer: A0=(a00,a10), A1=(a01,a11), C=(c0,c1)
__device__ __half2 g_fold_h[NPARH];

// Fold scale/shift of layer l into layer l+1's weights/bias.
// Layer 0 unclipped; layers 1..31 have W,b clipped to [-5,5].
__global__ void fold_kernel(const float* __restrict__ W, const float* __restrict__ b,
                            const float* __restrict__ scale, const float* __restrict__ shift,
                            const float* __restrict__ W_out, const float* __restrict__ b_out) {
    if (threadIdx.x == 0 && blockIdx.x == 0) {
        float sp0 = 1.0f, sp1 = 1.0f, shp0 = 0.0f, shp1 = 0.0f;
        for (int l = 0; l < NLAYERS; ++l) {
            float w00 = W[l * 4 + 0], w01 = W[l * 4 + 1];
            float w10 = W[l * 4 + 2], w11 = W[l * 4 + 3];
            float bb0 = b[l * 2 + 0], bb1 = b[l * 2 + 1];
            if (l > 0) {
                w00 = fminf(fmaxf(w00, -5.0f), 5.0f);
                w01 = fminf(fmaxf(w01, -5.0f), 5.0f);
                w10 = fminf(fmaxf(w10, -5.0f), 5.0f);
                w11 = fminf(fmaxf(w11, -5.0f), 5.0f);
                bb0 = fminf(fmaxf(bb0, -5.0f), 5.0f);
                bb1 = fminf(fmaxf(bb1, -5.0f), 5.0f);
            }
            float a00 = w00 * sp0, a01 = w01 * sp1, c0 = w00 * shp0 + w01 * shp1 + bb0;
            float a10 = w10 * sp0, a11 = w11 * sp1, c1 = w10 * shp0 + w11 * shp1 + bb1;
            g_fold[l * 6 + 0] = a00;
            g_fold[l * 6 + 1] = a01;
            g_fold[l * 6 + 2] = c0;
            g_fold[l * 6 + 3] = a10;
            g_fold[l * 6 + 4] = a11;
            g_fold[l * 6 + 5] = c1;
            g_fold_h[l * 3 + 0] = __floats2half2_rn(a00, a10);
            g_fold_h[l * 3 + 1] = __floats2half2_rn(a01, a11);
            g_fold_h[l * 3 + 2] = __floats2half2_rn(c0, c1);
            sp0 = scale[l * 2 + 0]; sp1 = scale[l * 2 + 1];
            shp0 = shift[l * 2 + 0]; shp1 = shift[l * 2 + 1];
        }
        float wo0 = W_out[0], wo1 = W_out[1];
        g_fold[NLAYERS * 6 + 0] = wo0 * sp0;
        g_fold[NLAYERS * 6 + 1] = wo1 * sp1;
        g_fold[NLAYERS * 6 + 2] = wo0 * shp0 + wo1 * shp1 + b_out[0];
    }
}

// Hardware tanh, scalar fp32: one MUFU op.
__device__ __forceinline__ float htanh(float x) {
    float y;
    asm("tanh.approx.f32 %0, %1;" : "=f"(y) : "f"(x));
    return y;
}

// Hardware tanh, packed fp16x2: one MUFU op computes TWO tanhs.
__device__ __forceinline__ __half2 htanh2(__half2 x) {
    uint32_t xi = *reinterpret_cast<uint32_t*>(&x);
    uint32_t yi;
    asm("tanh.approx.f16x2 %0, %1;" : "=r"(yi) : "r"(xi));
    return *reinterpret_cast<__half2*>(&yi);
}

__global__ void __launch_bounds__(TPB)
model_kernel(const float4* __restrict__ x4, float2* __restrict__ out2, int n4) {
    __shared__ float sp[NPAR];
    __shared__ __half2 sph[NPARH];
    for (int i = threadIdx.x; i < NPAR; i += TPB) sp[i] = g_fold[i];
    for (int i = threadIdx.x; i < NPARH; i += TPB) sph[i] = g_fold_h[i];
    __syncthreads();

    const int T = gridDim.x * TPB;
    const int tid = blockIdx.x * TPB + threadIdx.x;

    const int R = 2 * V4_PER_THREAD;   // 8 rows per thread
    __half2 H[R];                      // packed state (h0, h1) per row
    int idx[V4_PER_THREAD];
    bool valid[V4_PER_THREAD];

    // ---- Layer 0 in fp32 (x is fp32; unclipped weights), pack -> fp16 tanh ----
    {
        const float a00 = sp[0], a01 = sp[1], c0 = sp[2];
        const float a10 = sp[3], a11 = sp[4], c1 = sp[5];
#pragma unroll
        for (int k = 0; k < V4_PER_THREAD; ++k) {
            idx[k] = tid + k * T;       // coalesced
            valid[k] = idx[k] < n4;
            float4 v = valid[k] ? x4[idx[k]] : make_float4(0.f, 0.f, 0.f, 0.f);
            // row 2k: (v.x, v.y); row 2k+1: (v.z, v.w)
            float z0a = fmaf(a00, v.x, fmaf(a01, v.y, c0));
            float z1a = fmaf(a10, v.x, fmaf(a11, v.y, c1));
            float z0b = fmaf(a00, v.z, fmaf(a01, v.w, c0));
            float z1b = fmaf(a10, v.z, fmaf(a11, v.w, c1));
            H[2 * k + 0] = htanh2(__floats2half2_rn(z0a, z1a));
            H[2 * k + 1] = htanh2(__floats2half2_rn(z0b, z1b));
        }
    }

    // ---- Layers 1..29 fully packed fp16: 2 HFMA2 + 1 MUFU.TANH.f16x2 per row ----
#pragma unroll 1   // keep rolled: tiny body stays in L0 I$
    for (int l = FP16_FIRST; l < FP16_LAST; ++l) {
        const __half2 A0 = sph[l * 3 + 0];   // (a00, a10)
        const __half2 A1 = sph[l * 3 + 1];   // (a01, a11)
        const __half2 C  = sph[l * 3 + 2];   // (c0,  c1)
#pragma unroll
        for (int r = 0; r < R; ++r) {
            __half2 hlo = __low2half2(H[r]);    // (h0, h0)
            __half2 hhi = __high2half2(H[r]);   // (h1, h1)
            __half2 Z = __hfma2(A0, hlo, __hfma2(A1, hhi, C));
            H[r] = htanh2(Z);
        }
    }

    // ---- Layers 30..31 in fp32 (undamped error path to output) ----
    float h0[R], h1[R];
#pragma unroll
    for (int r = 0; r < R; ++r) {
        h0[r] = __low2float(H[r]);
        h1[r] = __high2float(H[r]);
    }
#pragma unroll
    for (int l = FP16_LAST; l < NLAYERS; ++l) {
        const float a00 = sp[l * 6 + 0], a01 = sp[l * 6 + 1], c0 = sp[l * 6 + 2];
        const float a10 = sp[l * 6 + 3], a11 = sp[l * 6 + 4], c1 = sp[l * 6 + 5];
#pragma unroll
        for (int r = 0; r < R; ++r) {
            float z0 = fmaf(a00, h0[r], fmaf(a01, h1[r], c0));
            float z1 = fmaf(a10, h0[r], fmaf(a11, h1[r], c1));
            h0[r] = htanh(z0);
            h1[r] = htanh(z1);
        }
    }

    const float wo0 = sp[NLAYERS * 6 + 0], wo1 = sp[NLAYERS * 6 + 1], bo = sp[NLAYERS * 6 + 2];
#pragma unroll
    for (int k = 0; k < V4_PER_THREAD; ++k) {
        if (valid[k]) {
            float2 o;
            o.x = fmaf(wo0, h0[2 * k + 0], fmaf(wo1, h1[2 * k + 0], bo));
            o.y = fmaf(wo0, h0[2 * k + 1], fmaf(wo1, h1[2 * k + 1], bo));
            out2[idx[k]] = o;
        }
    }
}

extern "C" void kernel_launch(void* const* d_in, const int* in_sizes, int n_in,
                              void* d_out, int out_size) {
    const float* x     = (const float*)d_in[0];
    const float* W     = (const float*)d_in[1];
    const float* b     = (const float*)d_in[2];
    const float* scale = (const float*)d_in[3];
    const float* shift = (const float*)d_in[4];
    const float* W_out = (const float*)d_in[5];
    const float* b_out = (const float*)d_in[6];

    fold_kernel<<<1, 32>>>(W, b, scale, shift, W_out, b_out);

    const int B  = in_sizes[0] / 2;   // rows
    const int n4 = B / 2;             // float4 count (2 rows per float4)
    const long long totalThreads = ((long long)n4 + V4_PER_THREAD - 1) / V4_PER_THREAD;
    const int blocks = (int)((totalThreads + TPB - 1) / TPB);

    model_kernel<<<blocks, TPB>>>((const float4*)x, (float2*)d_out, n4);
}

// round 6
// speedup vs baseline: 4.3438x; 2.3128x over previous
#include <cuda_runtime.h>
#include <stdint.h>

#define NLAYERS 32
#define NPAR (NLAYERS * 6 + 3)
#define TPB 256
#define V4_PER_THREAD 4   // 4 float4 = 8 rows per thread
#define LUTN 1024         // LUT grid per axis over [-1,1]^2

// Folded fp32 parameters: per layer {a00, a01, c0, a10, a11, c1}; then {wo0, wo1, bo}
__device__ float g_fold[NPAR];
// Scalar LUT: G[i*LUTN+j] = G(t0=grid_j, t1=grid_i)   (4 MB)
__device__ float g_G[LUTN * LUTN];
// Quad LUT: per cell, the 2x2 corner neighborhood as one aligned float4 (16 MB)
//   q.x=G[i][j]  q.y=G[i][j+1]  q.z=G[i+1][j]  q.w=G[i+1][j+1]
__device__ float4 g_Q[LUTN * LUTN];

// Fold scale/shift of layer l into layer l+1's weights/bias.
// Layer 0 unclipped; layers 1..31 have W,b clipped to [-5,5].
__global__ void fold_kernel(const float* __restrict__ W, const float* __restrict__ b,
                            const float* __restrict__ scale, const float* __restrict__ shift,
                            const float* __restrict__ W_out, const float* __restrict__ b_out) {
    if (threadIdx.x == 0 && blockIdx.x == 0) {
        float sp0 = 1.0f, sp1 = 1.0f, shp0 = 0.0f, shp1 = 0.0f;
        for (int l = 0; l < NLAYERS; ++l) {
            float w00 = W[l * 4 + 0], w01 = W[l * 4 + 1];
            float w10 = W[l * 4 + 2], w11 = W[l * 4 + 3];
            float bb0 = b[l * 2 + 0], bb1 = b[l * 2 + 1];
            if (l > 0) {
                w00 = fminf(fmaxf(w00, -5.0f), 5.0f);
                w01 = fminf(fmaxf(w01, -5.0f), 5.0f);
                w10 = fminf(fmaxf(w10, -5.0f), 5.0f);
                w11 = fminf(fmaxf(w11, -5.0f), 5.0f);
                bb0 = fminf(fmaxf(bb0, -5.0f), 5.0f);
                bb1 = fminf(fmaxf(bb1, -5.0f), 5.0f);
            }
            g_fold[l * 6 + 0] = w00 * sp0;
            g_fold[l * 6 + 1] = w01 * sp1;
            g_fold[l * 6 + 2] = w00 * shp0 + w01 * shp1 + bb0;
            g_fold[l * 6 + 3] = w10 * sp0;
            g_fold[l * 6 + 4] = w11 * sp1;
            g_fold[l * 6 + 5] = w10 * shp0 + w11 * shp1 + bb1;
            sp0 = scale[l * 2 + 0]; sp1 = scale[l * 2 + 1];
            shp0 = shift[l * 2 + 0]; shp1 = shift[l * 2 + 1];
        }
        float wo0 = W_out[0], wo1 = W_out[1];
        g_fold[NLAYERS * 6 + 0] = wo0 * sp0;
        g_fold[NLAYERS * 6 + 1] = wo1 * sp1;
        g_fold[NLAYERS * 6 + 2] = wo0 * shp0 + wo1 * shp1 + b_out[0];
    }
}

// Hardware tanh: one MUFU op.
__device__ __forceinline__ float htanh(float x) {
    float y;
    asm("tanh.approx.f32 %0, %1;" : "=f"(y) : "f"(x));
    return y;
}

// Build scalar LUT: G(t0,t1) = layers 1..31 (folded) + output head, fp32.
__global__ void __launch_bounds__(TPB)
build_G_kernel() {
    int idx = blockIdx.x * TPB + threadIdx.x;
    if (idx >= LUTN * LUTN) return;
    int i = idx >> 10;          // t1 index
    int j = idx & (LUTN - 1);   // t0 index (contiguous -> coalesced stores)
    const float inv = 2.0f / (float)(LUTN - 1);
    float h0 = fmaf((float)j, inv, -1.0f);
    float h1 = fmaf((float)i, inv, -1.0f);
#pragma unroll 1
    for (int l = 1; l < NLAYERS; ++l) {
        float a00 = g_fold[l * 6 + 0], a01 = g_fold[l * 6 + 1], c0 = g_fold[l * 6 + 2];
        float a10 = g_fold[l * 6 + 3], a11 = g_fold[l * 6 + 4], c1 = g_fold[l * 6 + 5];
        float z0 = fmaf(a00, h0, fmaf(a01, h1, c0));
        float z1 = fmaf(a10, h0, fmaf(a11, h1, c1));
        h0 = htanh(z0);
        h1 = htanh(z1);
    }
    float wo0 = g_fold[NLAYERS * 6 + 0], wo1 = g_fold[NLAYERS * 6 + 1], bo = g_fold[NLAYERS * 6 + 2];
    g_G[idx] = fmaf(wo0, h0, fmaf(wo1, h1, bo));
}

// Pack 2x2 neighborhoods into aligned float4 so the main kernel does ONE gather per row.
__global__ void __launch_bounds__(TPB)
build_Q_kernel() {
    int idx = blockIdx.x * TPB + threadIdx.x;
    if (idx >= LUTN * LUTN) return;
    int i = idx >> 10;
    int j = idx & (LUTN - 1);
    int ip = min(i + 1, LUTN - 1);
    int jp = min(j + 1, LUTN - 1);
    float4 q;
    q.x = g_G[i * LUTN + j];
    q.y = g_G[i * LUTN + jp];
    q.z = g_G[ip * LUTN + j];
    q.w = g_G[ip * LUTN + jp];
    g_Q[idx] = q;
}

// Main kernel: layer 0 (fp32) + bilinear LUT lookup of layers 1..31 + head.
__global__ void __launch_bounds__(TPB)
lookup_kernel(const float4* __restrict__ x4, float2* __restrict__ out2, int n4) {
    // layer-0 folded params (6 scalars, uniform)
    const float a00 = g_fold[0], a01 = g_fold[1], c0 = g_fold[2];
    const float a10 = g_fold[3], a11 = g_fold[4], c1 = g_fold[5];
    const float GS = 0.5f * (float)(LUTN - 1);   // [-1,1] -> [0, LUTN-1]

    const int T = gridDim.x * TPB;
    const int tid = blockIdx.x * TPB + threadIdx.x;

#pragma unroll
    for (int k = 0; k < V4_PER_THREAD; ++k) {
        int idx = tid + k * T;                  // coalesced
        if (idx >= n4) continue;
        float4 v = x4[idx];
        float2 o;
#pragma unroll
        for (int r = 0; r < 2; ++r) {
            float xi = (r == 0) ? v.x : v.z;
            float yi = (r == 0) ? v.y : v.w;
            float t0 = htanh(fmaf(a00, xi, fmaf(a01, yi, c0)));
            float t1 = htanh(fmaf(a10, xi, fmaf(a11, yi, c1)));
            float gx = fminf(fmaxf(fmaf(t0, GS, GS), 0.0f), (float)(LUTN - 1));
            float gy = fminf(fmaxf(fmaf(t1, GS, GS), 0.0f), (float)(LUTN - 1));
            int ix = min((int)gx, LUTN - 2);
            int iy = min((int)gy, LUTN - 2);
            float fx = gx - (float)ix;
            float fy = gy - (float)iy;
            float4 q = __ldg(&g_Q[iy * LUTN + ix]);   // one aligned 16B gather
            float top = fmaf(fx, q.y - q.x, q.x);
            float bot = fmaf(fx, q.w - q.z, q.z);
            float res = fmaf(fy, bot - top, top);
            if (r == 0) o.x = res; else o.y = res;
        }
        out2[idx] = o;
    }
}

extern "C" void kernel_launch(void* const* d_in, const int* in_sizes, int n_in,
                              void* d_out, int out_size) {
    const float* x     = (const float*)d_in[0];
    const float* W     = (const float*)d_in[1];
    const float* b     = (const float*)d_in[2];
    const float* scale = (const float*)d_in[3];
    const float* shift = (const float*)d_in[4];
    const float* W_out = (const float*)d_in[5];
    const float* b_out = (const float*)d_in[6];

    fold_kernel<<<1, 32>>>(W, b, scale, shift, W_out, b_out);

    const int lutBlocks = (LUTN * LUTN + TPB - 1) / TPB;
    build_G_kernel<<<lutBlocks, TPB>>>();
    build_Q_kernel<<<lutBlocks, TPB>>>();

    const int B  = in_sizes[0] / 2;   // rows
    const int n4 = B / 2;             // float4 count (2 rows per float4)
    const long long totalThreads = ((long long)n4 + V4_PER_THREAD - 1) / V4_PER_THREAD;
    const int blocks = (int)((totalThreads + TPB - 1) / TPB);

    lookup_kernel<<<blocks, TPB>>>((const float4*)x, (float2*)d_out, n4);
}

// round 9
// speedup vs baseline: 7.0555x; 1.6243x over previous
#include <cuda_runtime.h>
#include <stdint.h>

#define NLAYERS 32
#define NPAR (NLAYERS * 6 + 3)
#define TPB 256
#define LUTC 48            // cells per axis over [-1,1]^2
#define LUTG (LUTC + 1)    // corner grid points per axis
#define LPAD (LUTC + 1)    // smem row pitch in float4 (49 % 8 != 0 -> no column bank conflicts)
#define GRID_PERSIST 912   // ~6 blocks/SM on 148-152 SMs; grid-stride handles any SM count

// Folded fp32 parameters: per layer {a00, a01, c0, a10, a11, c1}; then {wo0, wo1, bo}
__device__ float g_fold[NPAR];
// Corner values G(t0,t1) on the LUTG x LUTG grid
__device__ float g_G[LUTG * LUTG];
// Per-cell 2x2 corner quad: q.x=G[i][j] q.y=G[i][j+1] q.z=G[i+1][j] q.w=G[i+1][j+1]
__device__ float4 g_Q[LUTC * LUTC];

// Parallel fold: layer l's folded params depend only on W[l],b[l] and scale/shift[l-1].
// Layer 0 unclipped; layers 1..31 clip W,b to [-5,5]. Thread NLAYERS folds the head.
__global__ void fold_kernel(const float* __restrict__ W, const float* __restrict__ b,
                            const float* __restrict__ scale, const float* __restrict__ shift,
                            const float* __restrict__ W_out, const float* __restrict__ b_out) {
    int l = threadIdx.x;
    if (l < NLAYERS) {
        float sp0 = 1.0f, sp1 = 1.0f, shp0 = 0.0f, shp1 = 0.0f;
        if (l > 0) {
            sp0 = scale[(l - 1) * 2 + 0]; sp1 = scale[(l - 1) * 2 + 1];
            shp0 = shift[(l - 1) * 2 + 0]; shp1 = shift[(l - 1) * 2 + 1];
        }
        float w00 = W[l * 4 + 0], w01 = W[l * 4 + 1];
        float w10 = W[l * 4 + 2], w11 = W[l * 4 + 3];
        float bb0 = b[l * 2 + 0], bb1 = b[l * 2 + 1];
        if (l > 0) {
            w00 = fminf(fmaxf(w00, -5.0f), 5.0f);
            w01 = fminf(fmaxf(w01, -5.0f), 5.0f);
            w10 = fminf(fmaxf(w10, -5.0f), 5.0f);
            w11 = fminf(fmaxf(w11, -5.0f), 5.0f);
            bb0 = fminf(fmaxf(bb0, -5.0f), 5.0f);
            bb1 = fminf(fmaxf(bb1, -5.0f), 5.0f);
        }
        g_fold[l * 6 + 0] = w00 * sp0;
        g_fold[l * 6 + 1] = w01 * sp1;
        g_fold[l * 6 + 2] = w00 * shp0 + w01 * shp1 + bb0;
        g_fold[l * 6 + 3] = w10 * sp0;
        g_fold[l * 6 + 4] = w11 * sp1;
        g_fold[l * 6 + 5] = w10 * shp0 + w11 * shp1 + bb1;
    } else if (l == NLAYERS) {
        float sp0 = scale[(NLAYERS - 1) * 2 + 0], sp1 = scale[(NLAYERS - 1) * 2 + 1];
        float shp0 = shift[(NLAYERS - 1) * 2 + 0], shp1 = shift[(NLAYERS - 1) * 2 + 1];
        float wo0 = W_out[0], wo1 = W_out[1];
        g_fold[NLAYERS * 6 + 0] = wo0 * sp0;
        g_fold[NLAYERS * 6 + 1] = wo1 * sp1;
        g_fold[NLAYERS * 6 + 2] = wo0 * shp0 + wo1 * shp1 + b_out[0];
    }
}

// Hardware tanh: one MUFU op.
__device__ __forceinline__ float htanh(float x) {
    float y;
    asm("tanh.approx.f32 %0, %1;" : "=f"(y) : "f"(x));
    return y;
}

// Corner evals: G(t0,t1) = layers 1..31 (folded) + head, fp32. Only 49x49 = 2401 evals.
__global__ void __launch_bounds__(TPB)
build_G_kernel() {
    int idx = blockIdx.x * TPB + threadIdx.x;
    if (idx >= LUTG * LUTG) return;
    int i = idx / LUTG;   // t1 index
    int j = idx % LUTG;   // t0 index
    const float inv = 2.0f / (float)LUTC;
    float h0 = fmaf((float)j, inv, -1.0f);
    float h1 = fmaf((float)i, inv, -1.0f);
#pragma unroll 1
    for (int l = 1; l < NLAYERS; ++l) {
        float a00 = g_fold[l * 6 + 0], a01 = g_fold[l * 6 + 1], c0 = g_fold[l * 6 + 2];
        float a10 = g_fold[l * 6 + 3], a11 = g_fold[l * 6 + 4], c1 = g_fold[l * 6 + 5];
        float z0 = fmaf(a00, h0, fmaf(a01, h1, c0));
        float z1 = fmaf(a10, h0, fmaf(a11, h1, c1));
        h0 = htanh(z0);
        h1 = htanh(z1);
    }
    float wo0 = g_fold[NLAYERS * 6 + 0], wo1 = g_fold[NLAYERS * 6 + 1], bo = g_fold[NLAYERS * 6 + 2];
    g_G[idx] = fmaf(wo0, h0, fmaf(wo1, h1, bo));
}

// Pack 2x2 corner neighborhoods into aligned float4 quads.
__global__ void __launch_bounds__(TPB)
build_Q_kernel() {
    int idx = blockIdx.x * TPB + threadIdx.x;
    if (idx >= LUTC * LUTC) return;
    int i = idx / LUTC;
    int j = idx % LUTC;
    float4 q;
    q.x = g_G[i * LUTG + j];
    q.y = g_G[i * LUTG + j + 1];
    q.z = g_G[(i + 1) * LUTG + j];
    q.w = g_G[(i + 1) * LUTG + j + 1];
    g_Q[idx] = q;
}

// Persistent main kernel: layer 0 (fp32) + one LDS.128 bilinear lookup per row.
__global__ void __launch_bounds__(TPB)
lookup_kernel(const float4* __restrict__ x4, float2* __restrict__ out2, int n4) {
    __shared__ float4 squad[LUTC * LPAD];   // 48 rows x 49 pitch x 16B = 37632 B

    // Cooperative, coalesced smem fill (quad table is tiny: 36 KB from L2).
    for (int t = threadIdx.x; t < LUTC * LUTC; t += TPB) {
        int i = t / LUTC, j = t % LUTC;
        squad[i * LPAD + j] = g_Q[t];
    }
    const float a00 = g_fold[0], a01 = g_fold[1], c0 = g_fold[2];
    const float a10 = g_fold[3], a11 = g_fold[4], c1 = g_fold[5];
    __syncthreads();

    const float GS = 0.5f * (float)LUTC;       // t in [-1,1] -> [0, LUTC]
    const int stride = gridDim.x * TPB;
    int idx = blockIdx.x * TPB + threadIdx.x;

    // Main unrolled-by-4 grid-stride loop: 4 front-batched LDG.128 for MLP.
    for (; idx + 3 * stride < n4; idx += 4 * stride) {
        float4 v[4];
#pragma unroll
        for (int k = 0; k < 4; ++k) v[k] = x4[idx + k * stride];
#pragma unroll
        for (int k = 0; k < 4; ++k) {
            float2 o;
#pragma unroll
            for (int r = 0; r < 2; ++r) {
                float xi = (r == 0) ? v[k].x : v[k].z;
                float yi = (r == 0) ? v[k].y : v[k].w;
                float t0 = htanh(fmaf(a00, xi, fmaf(a01, yi, c0)));
                float t1 = htanh(fmaf(a10, xi, fmaf(a11, yi, c1)));
                float gx = fminf(fmaxf(fmaf(t0, GS, GS), 0.0f), (float)LUTC);
                float gy = fminf(fmaxf(fmaf(t1, GS, GS), 0.0f), (float)LUTC);
                int ix = min((int)gx, LUTC - 1);
                int iy = min((int)gy, LUTC - 1);
                float fx = gx - (float)ix;
                float fy = gy - (float)iy;
                float4 q = squad[iy * LPAD + ix];          // one LDS.128
                float top = fmaf(fx, q.y - q.x, q.x);
                float bot = fmaf(fx, q.w - q.z, q.z);
                float res = fmaf(fy, bot - top, top);
                if (r == 0) o.x = res; else o.y = res;
            }
            out2[idx + k * stride] = o;
        }
    }
    // Remainder
    for (; idx < n4; idx += stride) {
        float4 v = x4[idx];
        float2 o;
#pragma unroll
        for (int r = 0; r < 2; ++r) {
            float xi = (r == 0) ? v.x : v.z;
            float yi = (r == 0) ? v.y : v.w;
            float t0 = htanh(fmaf(a00, xi, fmaf(a01, yi, c0)));
            float t1 = htanh(fmaf(a10, xi, fmaf(a11, yi, c1)));
            float gx = fminf(fmaxf(fmaf(t0, GS, GS), 0.0f), (float)LUTC);
            float gy = fminf(fmaxf(fmaf(t1, GS, GS), 0.0f), (float)LUTC);
            int ix = min((int)gx, LUTC - 1);
            int iy = min((int)gy, LUTC - 1);
            float fx = gx - (float)ix;
            float fy = gy - (float)iy;
            float4 q = squad[iy * LPAD + ix];
            float top = fmaf(fx, q.y - q.x, q.x);
            float bot = fmaf(fx, q.w - q.z, q.z);
            float res = fmaf(fy, bot - top, top);
            if (r == 0) o.x = res; else o.y = res;
        }
        out2[idx] = o;
    }
}

extern "C" void kernel_launch(void* const* d_in, const int* in_sizes, int n_in,
                              void* d_out, int out_size) {
    const float* x     = (const float*)d_in[0];
    const float* W     = (const float*)d_in[1];
    const float* b     = (const float*)d_in[2];
    const float* scale = (const float*)d_in[3];
    const float* shift = (const float*)d_in[4];
    const float* W_out = (const float*)d_in[5];
    const float* b_out = (const float*)d_in[6];

    fold_kernel<<<1, 64>>>(W, b, scale, shift, W_out, b_out);
    build_G_kernel<<<(LUTG * LUTG + TPB - 1) / TPB, TPB>>>();
    build_Q_kernel<<<(LUTC * LUTC + TPB - 1) / TPB, TPB>>>();

    const int B  = in_sizes[0] / 2;   // rows
    const int n4 = B / 2;             // float4 count (2 rows per float4)

    lookup_kernel<<<GRID_PERSIST, TPB>>>((const float4*)x, (float2*)d_out, n4);
}

// round 10
// speedup vs baseline: 10.4988x; 1.4880x over previous
#include <cuda_runtime.h>
#include <stdint.h>

#define NLAYERS 32
#define NPAR (NLAYERS * 6 + 3)
#define TPB 256
#define LUTC 32            // cells per axis over [-1,1]^2
#define LUTG (LUTC + 1)    // corner grid points per axis
#define LPAD (LUTC + 1)    // smem row pitch in float4 units (33: odd -> kills column-walk conflicts)
#define GRID_PERSIST 1184  // ~8 blocks/SM target; grid-stride tolerates any residency

// Folded fp32 parameters: per layer {a00, a01, c0, a10, a11, c1}; then {wo0, wo1, bo}
__device__ float g_fold[NPAR];
// Per-cell 2x2 corner quad: q.x=G[i][j] q.y=G[i][j+1] q.z=G[i+1][j] q.w=G[i+1][j+1]
__device__ float4 g_Q[LUTC * LUTC];

// Hardware tanh: one MUFU op.
__device__ __forceinline__ float htanh(float x) {
    float y;
    asm("tanh.approx.f32 %0, %1;" : "=f"(y) : "f"(x));
    return y;
}

// ONE fused prep kernel (single block, 1024 threads):
//   phase 1: fold scale/shift into next layer's weights (33 threads)
//   phase 2: evaluate G on the 33x33 corner grid (1089 evals)
//   phase 3: pack 2x2 corner quads (1024 cells)
__global__ void __launch_bounds__(1024)
prep_kernel(const float* __restrict__ W, const float* __restrict__ b,
            const float* __restrict__ scale, const float* __restrict__ shift,
            const float* __restrict__ W_out, const float* __restrict__ b_out) {
    __shared__ float sf[NPAR];
    __shared__ float sG[LUTG * LUTG];
    int t = threadIdx.x;

    // --- phase 1: parallel fold. Layer l uses W[l],b[l] and scale/shift[l-1].
    // Layer 0 unclipped; layers 1..31 clip W,b to [-5,5]. Thread NLAYERS folds the head.
    if (t < NLAYERS) {
        float sp0 = 1.0f, sp1 = 1.0f, shp0 = 0.0f, shp1 = 0.0f;
        if (t > 0) {
            sp0 = scale[(t - 1) * 2 + 0]; sp1 = scale[(t - 1) * 2 + 1];
            shp0 = shift[(t - 1) * 2 + 0]; shp1 = shift[(t - 1) * 2 + 1];
        }
        float w00 = W[t * 4 + 0], w01 = W[t * 4 + 1];
        float w10 = W[t * 4 + 2], w11 = W[t * 4 + 3];
        float bb0 = b[t * 2 + 0], bb1 = b[t * 2 + 1];
        if (t > 0) {
            w00 = fminf(fmaxf(w00, -5.0f), 5.0f);
            w01 = fminf(fmaxf(w01, -5.0f), 5.0f);
            w10 = fminf(fmaxf(w10, -5.0f), 5.0f);
            w11 = fminf(fmaxf(w11, -5.0f), 5.0f);
            bb0 = fminf(fmaxf(bb0, -5.0f), 5.0f);
            bb1 = fminf(fmaxf(bb1, -5.0f), 5.0f);
        }
        sf[t * 6 + 0] = w00 * sp0;
        sf[t * 6 + 1] = w01 * sp1;
        sf[t * 6 + 2] = w00 * shp0 + w01 * shp1 + bb0;
        sf[t * 6 + 3] = w10 * sp0;
        sf[t * 6 + 4] = w11 * sp1;
        sf[t * 6 + 5] = w10 * shp0 + w11 * shp1 + bb1;
    } else if (t == NLAYERS) {
        float sp0 = scale[(NLAYERS - 1) * 2 + 0], sp1 = scale[(NLAYERS - 1) * 2 + 1];
        float shp0 = shift[(NLAYERS - 1) * 2 + 0], shp1 = shift[(NLAYERS - 1) * 2 + 1];
        float wo0 = W_out[0], wo1 = W_out[1];
        sf[NLAYERS * 6 + 0] = wo0 * sp0;
        sf[NLAYERS * 6 + 1] = wo1 * sp1;
        sf[NLAYERS * 6 + 2] = wo0 * shp0 + wo1 * shp1 + b_out[0];
    }
    __syncthreads();
    if (t < NPAR) g_fold[t] = sf[t];   // lookup kernel needs layer-0 params

    // --- phase 2: corner evals G(t0,t1) = layers 1..31 (folded) + head, fp32.
    for (int idx = t; idx < LUTG * LUTG; idx += 1024) {
        int i = idx / LUTG;   // t1 index
        int j = idx % LUTG;   // t0 index
        const float inv = 2.0f / (float)LUTC;
        float h0 = fmaf((float)j, inv, -1.0f);
        float h1 = fmaf((float)i, inv, -1.0f);
#pragma unroll 1
        for (int l = 1; l < NLAYERS; ++l) {
            float a00 = sf[l * 6 + 0], a01 = sf[l * 6 + 1], c0 = sf[l * 6 + 2];
            float a10 = sf[l * 6 + 3], a11 = sf[l * 6 + 4], c1 = sf[l * 6 + 5];
            float z0 = fmaf(a00, h0, fmaf(a01, h1, c0));
            float z1 = fmaf(a10, h0, fmaf(a11, h1, c1));
            h0 = htanh(z0);
            h1 = htanh(z1);
        }
        float wo0 = sf[NLAYERS * 6 + 0], wo1 = sf[NLAYERS * 6 + 1], bo = sf[NLAYERS * 6 + 2];
        sG[idx] = fmaf(wo0, h0, fmaf(wo1, h1, bo));
    }
    __syncthreads();

    // --- phase 3: pack per-cell quads.
    for (int idx = t; idx < LUTC * LUTC; idx += 1024) {
        int i = idx / LUTC;
        int j = idx % LUTC;
        float4 q;
        q.x = sG[i * LUTG + j];
        q.y = sG[i * LUTG + j + 1];
        q.z = sG[(i + 1) * LUTG + j];
        q.w = sG[(i + 1) * LUTG + j + 1];
        g_Q[idx] = q;
    }
}

// Persistent main kernel: layer 0 (fp32) + one LDS.128 bilinear lookup per row.
// __launch_bounds__(TPB, 7): cap regs (~36) so occupancy isn't register-limited.
__global__ void __launch_bounds__(TPB, 7)
lookup_kernel(const float4* __restrict__ x4, float2* __restrict__ out2, int n4) {
    __shared__ float4 squad[LUTC * LPAD];   // 32 x 33 x 16B = 16896 B

    for (int t = threadIdx.x; t < LUTC * LUTC; t += TPB) {
        int i = t / LUTC, j = t % LUTC;
        squad[i * LPAD + j] = g_Q[t];
    }
    const float a00 = g_fold[0], a01 = g_fold[1], c0 = g_fold[2];
    const float a10 = g_fold[3], a11 = g_fold[4], c1 = g_fold[5];
    __syncthreads();

    const float GS = 0.5f * (float)LUTC;       // t in [-1,1] -> [0, LUTC]
    const int stride = gridDim.x * TPB;
    int idx = blockIdx.x * TPB + threadIdx.x;

    // Main unrolled-by-4 grid-stride loop: 4 front-batched LDG.128 for MLP.
    for (; idx + 3 * stride < n4; idx += 4 * stride) {
        float4 v[4];
#pragma unroll
        for (int k = 0; k < 4; ++k) v[k] = x4[idx + k * stride];
#pragma unroll
        for (int k = 0; k < 4; ++k) {
            float2 o;
#pragma unroll
            for (int r = 0; r < 2; ++r) {
                float xi = (r == 0) ? v[k].x : v[k].z;
                float yi = (r == 0) ? v[k].y : v[k].w;
                float t0 = htanh(fmaf(a00, xi, fmaf(a01, yi, c0)));
                float t1 = htanh(fmaf(a10, xi, fmaf(a11, yi, c1)));
                float gx = fminf(fmaxf(fmaf(t0, GS, GS), 0.0f), (float)LUTC);
                float gy = fminf(fmaxf(fmaf(t1, GS, GS), 0.0f), (float)LUTC);
                int ix = min((int)gx, LUTC - 1);
                int iy = min((int)gy, LUTC - 1);
                float fx = gx - (float)ix;
                float fy = gy - (float)iy;
                float4 q = squad[iy * LPAD + ix];          // one LDS.128
                float top = fmaf(fx, q.y - q.x, q.x);
                float bot = fmaf(fx, q.w - q.z, q.z);
                float res = fmaf(fy, bot - top, top);
                if (r == 0) o.x = res; else o.y = res;
            }
            out2[idx + k * stride] = o;
        }
    }
    // Remainder
    for (; idx < n4; idx += stride) {
        float4 v = x4[idx];
        float2 o;
#pragma unroll
        for (int r = 0; r < 2; ++r) {
            float xi = (r == 0) ? v.x : v.z;
            float yi = (r == 0) ? v.y : v.w;
            float t0 = htanh(fmaf(a00, xi, fmaf(a01, yi, c0)));
            float t1 = htanh(fmaf(a10, xi, fmaf(a11, yi, c1)));
            float gx = fminf(fmaxf(fmaf(t0, GS, GS), 0.0f), (float)LUTC);
            float gy = fminf(fmaxf(fmaf(t1, GS, GS), 0.0f), (float)LUTC);
            int ix = min((int)gx, LUTC - 1);
            int iy = min((int)gy, LUTC - 1);
            float fx = gx - (float)ix;
            float fy = gy - (float)iy;
            float4 q = squad[iy * LPAD + ix];
            float top = fmaf(fx, q.y - q.x, q.x);
            float bot = fmaf(fx, q.w - q.z, q.z);
            float res = fmaf(fy, bot - top, top);
            if (r == 0) o.x = res; else o.y = res;
        }
        out2[idx] = o;
    }
}

extern "C" void kernel_launch(void* const* d_in, const int* in_sizes, int n_in,
                              void* d_out, int out_size) {
    const float* x     = (const float*)d_in[0];
    const float* W     = (const float*)d_in[1];
    const float* b     = (const float*)d_in[2];
    const float* scale = (const float*)d_in[3];
    const float* shift = (const float*)d_in[4];
    const float* W_out = (const float*)d_in[5];
    const float* b_out = (const float*)d_in[6];

    prep_kernel<<<1, 1024>>>(W, b, scale, shift, W_out, b_out);

    const int B  = in_sizes[0] / 2;   // rows
    const int n4 = B / 2;             // float4 count (2 rows per float4)

    lookup_kernel<<<GRID_PERSIST, TPB>>>((const float4*)x, (float2*)d_out, n4);
}